// round 10
// baseline (speedup 1.0000x reference)
#include <cuda_runtime.h>
#include <math.h>

#define B_ 64
#define T_ 200
#define L_ 100
#define S_ 8
#define XC_ 16
#define H_ 256
#define W_ 128
#define O_ 8

#define NTHREADS 512

typedef unsigned long long u64;

// 2MB packed W2: for h in 0..255, pp in 0..7, k in 0..127:
//   c_lo = (pp&3) + 8*(pp>>2), c_hi = c_lo + 4
//   W2P[((h*8+pp)*128 + k)*2 + 0] = w2[(h*16+c_lo)*128 + k]
//   W2P[((h*8+pp)*128 + k)*2 + 1] = w2[(h*16+c_hi)*128 + k]
#define W2P_ELEMS (2 * 128 * 8 * 256)   // 524288 floats
__device__ float g_W2P[W2P_ELEMS];

// ---------------- smem layout (floats) ----------------
#define OFF_W0 0            // 32768  (mlp_w0 128x256)
#define OFF_W1 32768        // 16384  (mlp_w1 128x128)
#define OFF_B2 49152        // 4096
#define OFF_b0 53248        // 128
#define OFF_b1 53376        // 128
#define OFF_bn 53504        // 256
#define OFF_z  53760        // 256
#define OFF_zt 54016        // 256
#define OFF_a0 54272        // 128
#define OFF_a1 54400        // 128
#define OFF_k  54528        // 1536  (k-buffers; aliases GRU gate scratch 1024)
#define OFF_dx 56064        // 16
#define OFF_x  56080        // 32
#define OFF_ms 56112        // 8
#define SMEM_FLOATS 56120   // 224480 bytes

// ---------------- round-2 FROZEN math (bit-exact) ----------------
__device__ __forceinline__ float warp_red(float v) {
    v += __shfl_xor_sync(0xffffffffu, v, 16);
    v += __shfl_xor_sync(0xffffffffu, v, 8);
    v += __shfl_xor_sync(0xffffffffu, v, 4);
    v += __shfl_xor_sync(0xffffffffu, v, 2);
    v += __shfl_xor_sync(0xffffffffu, v, 1);
    return v;
}

__device__ __forceinline__ float softplus_(float x) {
    float e = __expf(-fabsf(x));
    return fmaxf(x, 0.0f) + __logf(1.0f + e);
}

__device__ __forceinline__ float sigmoid_(float x) {
    return 1.0f / (1.0f + __expf(-x));
}

// ---------------- packed f32x2 helpers (per-component == scalar fma.rn/add.rn) ----
__device__ __forceinline__ u64 ffma2(u64 a, u64 b, u64 c) {
    u64 d;
    asm("fma.rn.f32x2 %0, %1, %2, %3;" : "=l"(d) : "l"(a), "l"(b), "l"(c));
    return d;
}

__device__ __forceinline__ u64 add2(u64 a, u64 b) {
    u64 d;
    asm("add.rn.f32x2 %0, %1, %2;" : "=l"(d) : "l"(a), "l"(b));
    return d;
}

__device__ __forceinline__ u64 dup2(float v) {
    u64 d;
    asm("mov.b64 %0, {%1, %1};" : "=l"(d) : "f"(v));
    return d;
}

__device__ __forceinline__ float2 unpack2(u64 a) {
    float2 r;
    asm("mov.b64 {%0,%1}, %2;" : "=f"(r.x), "=f"(r.y) : "l"(a));
    return r;
}

__device__ __forceinline__ u64 shfl64(u64 v, int m) {
    unsigned lo = (unsigned)v, hi = (unsigned)(v >> 32);
    lo = __shfl_xor_sync(0xffffffffu, lo, m);
    hi = __shfl_xor_sync(0xffffffffu, hi, m);
    return ((u64)hi << 32) | lo;
}

// ---------------- vf: 1 batch, 16 warps ----------------
// Per-row arithmetic verbatim round 2; stage 3 = f32x2 row-pair packing with
// per-CTA rotated h-order (decorrelates CTAs in L2) + double-buffered prefetch.
__device__ void vf_eval(float* sm, float* __restrict__ kout, int wid, int lane,
                        int rot) {
    const int g = lane >> 3;
    const int l8 = lane & 7;
    const int odd = l8 & 1;
    const int hbase = wid * 16;

    const float* sW0 = sm + OFF_W0;
    const float* sW1 = sm + OFF_W1;
    const float* sB2 = sm + OFF_B2;
    const float* sb0 = sm + OFF_b0;
    const float* sb1 = sm + OFF_b1;
    float* sa0 = sm + OFF_a0;
    float* sa1 = sm + OFF_a1;
    const float* szt = sm + OFF_zt;
    const float* sdx = sm + OFF_dx;

    // ---- prologue: prefetch first stage-3 unit (i=rot, q=0) ----
    // W2P loads are independent of a1, so they overlap stages 1/2.
    float4 buf0[8], buf1[8];
    {
        const float* p = g_W2P + (((hbase + rot) * 8 + g) << 8) + 8 * l8;
#pragma unroll
        for (int j = 0; j < 8; j++)
            buf0[j] = __ldg((const float4*)(p + (j >> 1) * 64 + (j & 1) * 4));
    }

    // ---- stage 1: a0 (128 rows x 256), rows stride 16 over warps ----
    for (int row = wid; row < W_; row += 16) {
        const float* wr = sW0 + row * H_;
        float v = 0.0f;
#pragma unroll
        for (int k = 0; k < 8; k++) v = fmaf(wr[k * 32 + lane], szt[k * 32 + lane], v);
        v = warp_red(v);
        if (lane == 0) sa0[row] = softplus_(v + sb0[row]);
    }
    __syncthreads();

    // ---- stage 2: a1 (128 rows x 128) ----
    for (int row = wid; row < W_; row += 16) {
        const float* wr = sW1 + row * W_;
        float v = 0.0f;
#pragma unroll
        for (int k = 0; k < 4; k++) v = fmaf(wr[k * 32 + lane], sa0[k * 32 + lane], v);
        v = warp_red(v);
        if (lane == 0) sa1[row] = softplus_(v + sb1[row]);
    }
    __syncthreads();

    // ---- stage 3: rotated, double-buffered row-pair packed W2 matvec ----
    u64 a1d[16];
    {
        const float4* a1v = (const float4*)sa1;
#pragma unroll
        for (int jj = 0; jj < 4; jj++) {
            float4 t = a1v[jj * 8 + l8];
            a1d[4 * jj + 0] = dup2(t.x);
            a1d[4 * jj + 1] = dup2(t.y);
            a1d[4 * jj + 2] = dup2(t.z);
            a1d[4 * jj + 3] = dup2(t.w);
        }
    }
    float dxsel[4];
#pragma unroll
    for (int it = 0; it < 4; it++) dxsel[it] = sdx[it * 4 + g];

    float ks = 0.0f;
#pragma unroll 4
    for (int uu = 0; uu < 32; uu++) {
        const int i = (((uu >> 1) + rot) & 15);
        const int q = uu & 1;
        float4* cur = (uu & 1) ? buf1 : buf0;
        float4* nxt = (uu & 1) ? buf0 : buf1;
        if (uu < 31) {
            const int ni = ((((uu + 1) >> 1) + rot) & 15);
            const int nq = (uu + 1) & 1;
            const float* p = g_W2P + (((hbase + ni) * 8 + g + 4 * nq) << 8) + 8 * l8;
#pragma unroll
            for (int j = 0; j < 8; j++)
                nxt[j] = __ldg((const float4*)(p + (j >> 1) * 64 + (j & 1) * 4));
        }
        // {s_lo, s_hi}; fma(w,a,0) == rn(w*a) == round-2 leading MUL
        u64 acc = 0ULL;
#pragma unroll
        for (int jj = 0; jj < 4; jj++) {
            const u64* ua = (const u64*)(cur + 2 * jj);
            const u64* ub = (const u64*)(cur + 2 * jj + 1);
            acc = ffma2(ua[0], a1d[4 * jj + 0], acc);
            acc = ffma2(ua[1], a1d[4 * jj + 1], acc);
            acc = ffma2(ub[0], a1d[4 * jj + 2], acc);
            acc = ffma2(ub[1], a1d[4 * jj + 3], acc);
        }
        // packed xor 1,2,4 reduce (component-wise == round-2 scalar tree)
        acc = add2(acc, shfl64(acc, 1));
        acc = add2(acc, shfl64(acc, 2));
        acc = add2(acc, shfl64(acc, 4));
        // one tanhf issue covers the pair: even lanes -> c_lo, odd -> c_hi
        float2 sv = unpack2(acc);
        int c = g + 8 * q + 4 * odd;
        float bb = sB2[(hbase + i) * 16 + c];
        float x = (odd ? sv.y : sv.x) + bb;
        float tv = tanhf(x);
        float tw = __shfl_xor_sync(0xffffffffu, tv, 1);
        float tvA = odd ? tw : tv;  // tanh for c_lo  (it = 2q)
        float tvB = odd ? tv : tw;  // tanh for c_hi  (it = 2q+1)
        ks = fmaf(tvA, dxsel[2 * q], ks);
        ks = fmaf(tvB, dxsel[2 * q + 1], ks);
        if (q == 1) {
            // cross-group tree (round-2 xor8/xor16 order)
            ks += __shfl_xor_sync(0xffffffffu, ks, 8);
            ks += __shfl_xor_sync(0xffffffffu, ks, 16);
            if (lane == 0) kout[hbase + i] = ks;
            ks = 0.0f;
        }
    }
    __syncthreads();
}

// ---------------- W2 pack kernel (exactly W2P_ELEMS threads) ----------------
extern "C" __global__ void pack_w2_kernel(const float* __restrict__ w2) {
    int idx = blockIdx.x * blockDim.x + threadIdx.x;
    int half = idx & 1;
    int k = (idx >> 1) & 127;
    int pp = (idx >> 8) & 7;
    int h = idx >> 11;  // 0..255
    int c = (pp & 3) + 8 * (pp >> 2) + 4 * half;
    g_W2P[idx] = w2[(h * 16 + c) * 128 + k];
}

extern "C" __global__ void __launch_bounds__(NTHREADS, 1)
grucde_kernel(const float* __restrict__ y_past, const float* __restrict__ t,
              const float* __restrict__ cx, const float* __restrict__ wih,
              const float* __restrict__ whh, const float* __restrict__ gb,
              const float* __restrict__ gbn, const float* __restrict__ w0,
              const float* __restrict__ b0, const float* __restrict__ w1,
              const float* __restrict__ b1, const float* __restrict__ w2,
              const float* __restrict__ b2, const float* __restrict__ row_,
              const float* __restrict__ rob, float* __restrict__ out) {
    extern __shared__ float sm[];
    const int tid = threadIdx.x;
    const int wid = tid >> 5;
    const int lane = tid & 31;
    const int b = blockIdx.x;
    const int rot = b & 15;

    float* sz = sm + OFF_z;
    float* szt = sm + OFF_zt;
    float* sk = sm + OFF_k;
    float* sdx = sm + OFF_dx;
    float* sx = sm + OFF_x;
    float* sbn = sm + OFF_bn;
    float* sms = sm + OFF_ms;

    // ---- stage weights into SMEM ----
    {
        float4* d = (float4*)(sm + OFF_W0);
        const float4* s4 = (const float4*)w0;
        for (int i = tid; i < 8192; i += NTHREADS) d[i] = s4[i];
        d = (float4*)(sm + OFF_W1);
        s4 = (const float4*)w1;
        for (int i = tid; i < 4096; i += NTHREADS) d[i] = s4[i];
        d = (float4*)(sm + OFF_B2);
        s4 = (const float4*)b2;
        for (int i = tid; i < 1024; i += NTHREADS) d[i] = s4[i];
        if (tid < 128) {
            sm[OFF_b0 + tid] = b0[tid];
            sm[OFF_b1 + tid] = b1[tid];
        }
        if (tid < 256) {
            sbn[tid] = gbn[tid];
            sz[tid] = 0.0f;
        }
    }
    __syncthreads();

    // ============ GRU encoder: 100 sequential steps (round-2 per-row code) ============
    // Per-warp row order rotated per CTA (rows independent -> bit-exact).
    {
        float* sgA = sk;
        float* sgH = sk + 768;
        const int grot = (b * 3) % 48;
        for (int s = 0; s < L_; s++) {
            if (tid < 24) {
                float xv;
                if (tid < 8) xv = y_past[(b * L_ + s) * S_ + tid];
                else if (tid < 23) xv = cx[(b * T_ + s) * (XC_ - 1) + (tid - 8)];
                else xv = t[s];
                sx[tid] = xv;
            }
            __syncthreads();
            for (int jj = 0; jj < 48; jj++) {
                int idx = jj + grot;
                if (idx >= 48) idx -= 48;
                int row = wid + (idx << 4);
                float vi = (lane < 24) ? wih[row * 24 + lane] * sx[lane] : 0.0f;
                float vh = 0.0f;
                const float* wr = whh + row * 256;
#pragma unroll
                for (int k = 0; k < 8; k++) vh = fmaf(wr[k * 32 + lane], sz[k * 32 + lane], vh);
                if (row < 512) {
                    float v = warp_red(vi + vh);
                    if (lane == 0) sgA[row] = v + gb[row];
                } else {
                    vi = warp_red(vi);
                    vh = warp_red(vh);
                    if (lane == 0) {
                        sgA[row] = vi + gb[row];
                        sgH[row - 512] = vh;
                    }
                }
            }
            __syncthreads();
            if (tid < 256) {
                int i = tid;
                float r = sigmoid_(sgA[i]);
                float u = sigmoid_(sgA[256 + i]);
                float n = tanhf(fmaf(r, sgH[i] + sbn[i], sgA[512 + i]));
                sz[i] = n + u * (sz[i] - n);
            }
            __syncthreads();
        }
    }

    // readout: warps 0-7 -> channel wid (round-2 arithmetic)
    auto readout = [&](int idx) {
        if (wid < 8) {
            const float* wr = row_ + wid * 256;
            float v = 0.0f;
#pragma unroll
            for (int k = 0; k < 8; k++) v = fmaf(wr[k * 32 + lane], sz[k * 32 + lane], v);
            v = warp_red(v);
            if (lane == 0) out[(b * L_ + idx) * O_ + wid] = v + rob[wid];
        }
    };

    readout(0);

    // zero the k buffers (they aliased GRU scratch)
    for (int i = tid; i < 1536; i += NTHREADS) sk[i] = 0.0f;
    __syncthreads();

    // k-buffers (256 floats each); k5 reuses k1's slot (k1 dead by then)
    float* kb0 = sk;
    float* kb1 = sk + 256;
    float* kb2 = sk + 512;
    float* kb3 = sk + 768;
    float* kb4 = sk + 1024;
    float* kb5 = sk + 256;

    // ============ CDE: 99 intervals x 2 dopri5 substeps ============
    for (int iv = 0; iv < T_ - L_ - 1; iv++) {
        if (tid < 16) {
            int s = L_ + iv;
            float dtv = t[s + 1] - t[s];
            float x0v = (tid < 15) ? cx[(b * T_ + s) * 15 + tid] : t[s];
            float x1v = (tid < 15) ? cx[(b * T_ + s + 1) * 15 + tid] : t[s + 1];
            sdx[tid] = (x1v - x0v) / dtv;
            if (tid == 0) sms[0] = dtv;
        }
        __syncthreads();
        const float hs = sms[0] * 0.5f;

        for (int sub = 0; sub < 2; sub++) {
            // stage 0
            if (tid < 256) szt[tid] = sz[tid];
            __syncthreads();
            vf_eval(sm, kb0, wid, lane, rot);
            // stage 1
            if (tid < 256) szt[tid] = fmaf(hs * 0.2f, kb0[tid], sz[tid]);
            __syncthreads();
            vf_eval(sm, kb1, wid, lane, rot);
            // stage 2
            if (tid < 256) {
                float v = 0.075f * kb0[tid] + 0.225f * kb1[tid];
                szt[tid] = fmaf(hs, v, sz[tid]);
            }
            __syncthreads();
            vf_eval(sm, kb2, wid, lane, rot);
            // stage 3
            if (tid < 256) {
                float v = (44.0f / 45.0f) * kb0[tid] + (-56.0f / 15.0f) * kb1[tid] +
                          (32.0f / 9.0f) * kb2[tid];
                szt[tid] = fmaf(hs, v, sz[tid]);
            }
            __syncthreads();
            vf_eval(sm, kb3, wid, lane, rot);
            // stage 4
            if (tid < 256) {
                float v = (19372.0f / 6561.0f) * kb0[tid] + (-25360.0f / 2187.0f) * kb1[tid] +
                          (64448.0f / 6561.0f) * kb2[tid] + (-212.0f / 729.0f) * kb3[tid];
                szt[tid] = fmaf(hs, v, sz[tid]);
            }
            __syncthreads();
            vf_eval(sm, kb4, wid, lane, rot);
            // stage 5 (k1 consumed for the last time; k5 overwrites its slot)
            if (tid < 256) {
                float v = (9017.0f / 3168.0f) * kb0[tid] + (-355.0f / 33.0f) * kb1[tid] +
                          (46732.0f / 5247.0f) * kb2[tid] + (49.0f / 176.0f) * kb3[tid] +
                          (-5103.0f / 18656.0f) * kb4[tid];
                szt[tid] = fmaf(hs, v, sz[tid]);
            }
            __syncthreads();
            vf_eval(sm, kb5, wid, lane, rot);
            // combine
            if (tid < 256) {
                float v = (35.0f / 384.0f) * kb0[tid] + (500.0f / 1113.0f) * kb2[tid] +
                          (125.0f / 192.0f) * kb3[tid] + (-2187.0f / 6784.0f) * kb4[tid] +
                          (11.0f / 84.0f) * kb5[tid];
                sz[tid] = fmaf(hs, v, sz[tid]);
            }
            __syncthreads();
        }
        readout(iv + 1);
        __syncthreads();
    }
}

extern "C" void kernel_launch(void* const* d_in, const int* in_sizes, int n_in,
                              void* d_out, int out_size) {
    (void)in_sizes;
    (void)n_in;
    (void)out_size;
    const float* w2 = (const float*)d_in[11];
    pack_w2_kernel<<<W2P_ELEMS / 512, 512>>>(w2);
    const size_t smem_bytes = SMEM_FLOATS * sizeof(float);
    cudaFuncSetAttribute(grucde_kernel, cudaFuncAttributeMaxDynamicSharedMemorySize,
                         (int)smem_bytes);
    grucde_kernel<<<B_, NTHREADS, smem_bytes>>>(
        (const float*)d_in[0], (const float*)d_in[1], (const float*)d_in[2],
        (const float*)d_in[3], (const float*)d_in[4], (const float*)d_in[5],
        (const float*)d_in[6], (const float*)d_in[7], (const float*)d_in[8],
        (const float*)d_in[9], (const float*)d_in[10], (const float*)d_in[11],
        (const float*)d_in[12], (const float*)d_in[13], (const float*)d_in[14],
        (float*)d_out);
}

// round 15
// speedup vs baseline: 1.0884x; 1.0884x over previous
#include <cuda_runtime.h>
#include <math.h>

#define B_ 64
#define T_ 200
#define L_ 100
#define S_ 8
#define XC_ 16
#define H_ 256
#define W_ 128
#define O_ 8

#define NTHREADS 512

typedef unsigned long long u64;

// 2MB packed W2: for h in 0..255, pp in 0..7, k in 0..127:
//   c_lo = (pp&3) + 8*(pp>>2), c_hi = c_lo + 4
//   W2P[((h*8+pp)*128 + k)*2 + 0] = w2[(h*16+c_lo)*128 + k]
//   W2P[((h*8+pp)*128 + k)*2 + 1] = w2[(h*16+c_hi)*128 + k]
#define W2P_ELEMS (2 * 128 * 8 * 256)   // 524288 floats
__device__ float g_W2P[W2P_ELEMS];

// ---------------- smem layout (floats) ----------------
#define OFF_W0 0            // 32768  (mlp_w0 128x256)
#define OFF_W1 32768        // 16384  (mlp_w1 128x128)
#define OFF_B2 49152        // 4096
#define OFF_b0 53248        // 128
#define OFF_b1 53376        // 128
#define OFF_bn 53504        // 256
#define OFF_z  53760        // 256
#define OFF_zt 54016        // 256
#define OFF_a0 54272        // 128
#define OFF_a1 54400        // 128
#define OFF_k  54528        // 1536  (k-buffers; aliases GRU gate scratch 1024)
#define OFF_dx 56064        // 16
#define OFF_x  56080        // 32
#define OFF_ms 56112        // 8
#define SMEM_FLOATS 56120   // 224480 bytes

// ---------------- round-2 FROZEN math (bit-exact) ----------------
__device__ __forceinline__ float warp_red(float v) {
    v += __shfl_xor_sync(0xffffffffu, v, 16);
    v += __shfl_xor_sync(0xffffffffu, v, 8);
    v += __shfl_xor_sync(0xffffffffu, v, 4);
    v += __shfl_xor_sync(0xffffffffu, v, 2);
    v += __shfl_xor_sync(0xffffffffu, v, 1);
    return v;
}

__device__ __forceinline__ float softplus_(float x) {
    float e = __expf(-fabsf(x));
    return fmaxf(x, 0.0f) + __logf(1.0f + e);
}

__device__ __forceinline__ float sigmoid_(float x) {
    return 1.0f / (1.0f + __expf(-x));
}

// ---------------- packed f32x2 helpers (per-component == scalar fma.rn/add.rn) ----
__device__ __forceinline__ u64 ffma2(u64 a, u64 b, u64 c) {
    u64 d;
    asm("fma.rn.f32x2 %0, %1, %2, %3;" : "=l"(d) : "l"(a), "l"(b), "l"(c));
    return d;
}

__device__ __forceinline__ u64 add2(u64 a, u64 b) {
    u64 d;
    asm("add.rn.f32x2 %0, %1, %2;" : "=l"(d) : "l"(a), "l"(b));
    return d;
}

__device__ __forceinline__ u64 dup2(float v) {
    u64 d;
    asm("mov.b64 %0, {%1, %1};" : "=l"(d) : "f"(v));
    return d;
}

__device__ __forceinline__ float2 unpack2(u64 a) {
    float2 r;
    asm("mov.b64 {%0,%1}, %2;" : "=f"(r.x), "=f"(r.y) : "l"(a));
    return r;
}

__device__ __forceinline__ u64 shfl64(u64 v, int m) {
    unsigned lo = (unsigned)v, hi = (unsigned)(v >> 32);
    lo = __shfl_xor_sync(0xffffffffu, lo, m);
    hi = __shfl_xor_sync(0xffffffffu, hi, m);
    return ((u64)hi << 32) | lo;
}

// ---------------- cluster helpers ----------------
__device__ __forceinline__ unsigned smem_addr_u32(const void* p) {
    unsigned a;
    asm("{ .reg .u64 t; cvta.to.shared.u64 t, %1; cvt.u32.u64 %0, t; }"
        : "=r"(a) : "l"(p));
    return a;
}

__device__ __forceinline__ unsigned cluster_rank_() {
    unsigned r;
    asm("mov.u32 %0, %%cluster_ctarank;" : "=r"(r));
    return r;
}

__device__ __forceinline__ unsigned mapa_shared(unsigned addr, unsigned rank) {
    unsigned r;
    asm("mapa.shared::cluster.u32 %0, %1, %2;" : "=r"(r) : "r"(addr), "r"(rank));
    return r;
}

__device__ __forceinline__ void st_cluster_f32(unsigned addr, float v) {
    asm volatile("st.shared::cluster.f32 [%0], %1;" :: "r"(addr), "f"(v) : "memory");
}

__device__ __forceinline__ void cluster_sync_() {
    asm volatile("barrier.cluster.arrive.aligned;" ::: "memory");
    asm volatile("barrier.cluster.wait.aligned;" ::: "memory");
}

// ---------------- vf split across a 2-CTA cluster ----------------
// rank r computes a0 rows [r*64, +64), a1 rows [r*64, +64), h in [r*128, +128);
// halves are pushed to the peer via DSMEM stores, cluster.sync between stages.
// Per-row arithmetic verbatim round 2 -> bit-exact.
__device__ void vf_eval(float* sm, int kofs, int wid, int lane, int rank,
                        unsigned peer_u32) {
    const int g = lane >> 3;
    const int l8 = lane & 7;
    const int odd = l8 & 1;

    const float* sW0 = sm + OFF_W0;
    const float* sW1 = sm + OFF_W1;
    const float* sB2 = sm + OFF_B2;
    const float* sb0 = sm + OFF_b0;
    const float* sb1 = sm + OFF_b1;
    float* sa0 = sm + OFF_a0;
    float* sa1 = sm + OFF_a1;
    const float* szt = sm + OFF_zt;
    const float* sdx = sm + OFF_dx;
    float* kout = sm + kofs;

    // ---- stage 1: a0 rows [rank*64, +64) : 4 rows per warp ----
    {
        const int lo = rank * 64;
        for (int row = lo + wid; row < lo + 64; row += 16) {
            const float* wr = sW0 + row * H_;
            float v = 0.0f;
#pragma unroll
            for (int k = 0; k < 8; k++) v = fmaf(wr[k * 32 + lane], szt[k * 32 + lane], v);
            v = warp_red(v);
            if (lane == 0) {
                float val = softplus_(v + sb0[row]);
                sa0[row] = val;
                st_cluster_f32(peer_u32 + 4u * (OFF_a0 + row), val);
            }
        }
    }
    cluster_sync_();

    // ---- stage 2: a1 rows [rank*64, +64) ----
    {
        const int lo = rank * 64;
        for (int row = lo + wid; row < lo + 64; row += 16) {
            const float* wr = sW1 + row * W_;
            float v = 0.0f;
#pragma unroll
            for (int k = 0; k < 4; k++) v = fmaf(wr[k * 32 + lane], sa0[k * 32 + lane], v);
            v = warp_red(v);
            if (lane == 0) {
                float val = softplus_(v + sb1[row]);
                sa1[row] = val;
                st_cluster_f32(peer_u32 + 4u * (OFF_a1 + row), val);
            }
        }
    }
    cluster_sync_();

    // ---- stage 3: h in [rank*128, +128): 8 h per warp, row-pair f32x2 packing ----
    u64 a1d[16];
    {
        const float4* a1v = (const float4*)sa1;
#pragma unroll
        for (int jj = 0; jj < 4; jj++) {
            float4 t = a1v[jj * 8 + l8];
            a1d[4 * jj + 0] = dup2(t.x);
            a1d[4 * jj + 1] = dup2(t.y);
            a1d[4 * jj + 2] = dup2(t.z);
            a1d[4 * jj + 3] = dup2(t.w);
        }
    }
    float dxsel[4];
#pragma unroll
    for (int it = 0; it < 4; it++) dxsel[it] = sdx[it * 4 + g];

    const int hbase = rank * 128 + wid * 8;
#pragma unroll 2
    for (int i = 0; i < 8; i++) {
        const int h = hbase + i;
        float ks = 0.0f;
#pragma unroll
        for (int q = 0; q < 2; q++) {
            const float* wp = g_W2P + ((h * 8 + g + 4 * q) << 8) + 8 * l8;
            u64 acc = 0ULL;  // {s_lo, s_hi}; fma(w,a,0) == rn(w*a) == round-2 leading MUL
#pragma unroll
            for (int jj = 0; jj < 4; jj++) {
                float4 wa = __ldg((const float4*)(wp + 64 * jj));
                float4 wb = __ldg((const float4*)(wp + 64 * jj + 4));
                const u64* ua = (const u64*)&wa;
                const u64* ub = (const u64*)&wb;
                acc = ffma2(ua[0], a1d[4 * jj + 0], acc);
                acc = ffma2(ua[1], a1d[4 * jj + 1], acc);
                acc = ffma2(ub[0], a1d[4 * jj + 2], acc);
                acc = ffma2(ub[1], a1d[4 * jj + 3], acc);
            }
            // packed xor 1,2,4 reduce (component-wise == round-2 scalar tree)
            acc = add2(acc, shfl64(acc, 1));
            acc = add2(acc, shfl64(acc, 2));
            acc = add2(acc, shfl64(acc, 4));
            // one tanhf issue covers the pair: even lanes -> c_lo, odd -> c_hi
            float2 sv = unpack2(acc);
            int c = g + 8 * q + 4 * odd;
            float bb = sB2[h * 16 + c];
            float x = (odd ? sv.y : sv.x) + bb;
            float tv = tanhf(x);
            float tw = __shfl_xor_sync(0xffffffffu, tv, 1);
            float tvA = odd ? tw : tv;  // tanh for c_lo  (it = 2q)
            float tvB = odd ? tv : tw;  // tanh for c_hi  (it = 2q+1)
            ks = fmaf(tvA, dxsel[2 * q], ks);
            ks = fmaf(tvB, dxsel[2 * q + 1], ks);
        }
        // cross-group tree (round-2 xor8/xor16 order)
        ks += __shfl_xor_sync(0xffffffffu, ks, 8);
        ks += __shfl_xor_sync(0xffffffffu, ks, 16);
        if (lane == 0) {
            kout[h] = ks;
            st_cluster_f32(peer_u32 + 4u * (kofs + h), ks);
        }
    }
    cluster_sync_();
}

// ---------------- W2 pack kernel (exactly W2P_ELEMS threads) ----------------
extern "C" __global__ void pack_w2_kernel(const float* __restrict__ w2) {
    int idx = blockIdx.x * blockDim.x + threadIdx.x;
    int half = idx & 1;
    int k = (idx >> 1) & 127;
    int pp = (idx >> 8) & 7;
    int h = idx >> 11;  // 0..255
    int c = (pp & 3) + 8 * (pp >> 2) + 4 * half;
    g_W2P[idx] = w2[(h * 16 + c) * 128 + k];
}

extern "C" __global__ void __launch_bounds__(NTHREADS, 1) __cluster_dims__(2, 1, 1)
grucde_kernel(const float* __restrict__ y_past, const float* __restrict__ t,
              const float* __restrict__ cx, const float* __restrict__ wih,
              const float* __restrict__ whh, const float* __restrict__ gb,
              const float* __restrict__ gbn, const float* __restrict__ w0,
              const float* __restrict__ b0, const float* __restrict__ w1,
              const float* __restrict__ b1, const float* __restrict__ w2,
              const float* __restrict__ b2, const float* __restrict__ row_,
              const float* __restrict__ rob, float* __restrict__ out) {
    extern __shared__ float sm[];
    const int tid = threadIdx.x;
    const int wid = tid >> 5;
    const int lane = tid & 31;
    const int b = blockIdx.x >> 1;           // batch = cluster id
    const int rank = (int)cluster_rank_();   // 0 or 1 within the cluster

    // peer smem base (u32 shared-window address of the other CTA's sm[0])
    const unsigned own_u32 = smem_addr_u32(sm);
    const unsigned peer_u32 = mapa_shared(own_u32, (unsigned)(rank ^ 1));

    float* sz = sm + OFF_z;
    float* szt = sm + OFF_zt;
    float* sk = sm + OFF_k;
    float* sdx = sm + OFF_dx;
    float* sx = sm + OFF_x;
    float* sbn = sm + OFF_bn;
    float* sms = sm + OFF_ms;

    // ---- stage weights into SMEM (both ranks: identical full copies) ----
    {
        float4* d = (float4*)(sm + OFF_W0);
        const float4* s4 = (const float4*)w0;
        for (int i = tid; i < 8192; i += NTHREADS) d[i] = s4[i];
        d = (float4*)(sm + OFF_W1);
        s4 = (const float4*)w1;
        for (int i = tid; i < 4096; i += NTHREADS) d[i] = s4[i];
        d = (float4*)(sm + OFF_B2);
        s4 = (const float4*)b2;
        for (int i = tid; i < 1024; i += NTHREADS) d[i] = s4[i];
        if (tid < 128) {
            sm[OFF_b0 + tid] = b0[tid];
            sm[OFF_b1 + tid] = b1[tid];
        }
        if (tid < 256) {
            sbn[tid] = gbn[tid];
            sz[tid] = 0.0f;
        }
    }
    __syncthreads();

    // ============ GRU encoder: 100 steps, computed REDUNDANTLY by both ranks ============
    // (identical inputs -> identical z; no cluster traffic needed)
    {
        float* sgA = sk;
        float* sgH = sk + 768;
        for (int s = 0; s < L_; s++) {
            if (tid < 24) {
                float xv;
                if (tid < 8) xv = y_past[(b * L_ + s) * S_ + tid];
                else if (tid < 23) xv = cx[(b * T_ + s) * (XC_ - 1) + (tid - 8)];
                else xv = t[s];
                sx[tid] = xv;
            }
            __syncthreads();
            for (int row = wid; row < 768; row += 16) {
                float vi = (lane < 24) ? wih[row * 24 + lane] * sx[lane] : 0.0f;
                float vh = 0.0f;
                const float* wr = whh + row * 256;
#pragma unroll
                for (int k = 0; k < 8; k++) vh = fmaf(wr[k * 32 + lane], sz[k * 32 + lane], vh);
                if (row < 512) {
                    float v = warp_red(vi + vh);
                    if (lane == 0) sgA[row] = v + gb[row];
                } else {
                    vi = warp_red(vi);
                    vh = warp_red(vh);
                    if (lane == 0) {
                        sgA[row] = vi + gb[row];
                        sgH[row - 512] = vh;
                    }
                }
            }
            __syncthreads();
            if (tid < 256) {
                int i = tid;
                float r = sigmoid_(sgA[i]);
                float u = sigmoid_(sgA[256 + i]);
                float n = tanhf(fmaf(r, sgH[i] + sbn[i], sgA[512 + i]));
                sz[i] = n + u * (sz[i] - n);
            }
            __syncthreads();
        }
    }

    // readout: rank 0 only (both ranks hold identical sz)
    auto readout = [&](int idx) {
        if (rank == 0 && wid < 8) {
            const float* wr = row_ + wid * 256;
            float v = 0.0f;
#pragma unroll
            for (int k = 0; k < 8; k++) v = fmaf(wr[k * 32 + lane], sz[k * 32 + lane], v);
            v = warp_red(v);
            if (lane == 0) out[(b * L_ + idx) * O_ + wid] = v + rob[wid];
        }
    };

    readout(0);

    // zero the k buffers (they aliased GRU scratch)
    for (int i = tid; i < 1536; i += NTHREADS) sk[i] = 0.0f;
    __syncthreads();
    // align ranks before any cross-CTA k writes can land
    cluster_sync_();

    // k-buffer float offsets from sm base; k5 reuses k1's slot (k1 dead by then)
    const int kofs0 = OFF_k;
    const int kofs1 = OFF_k + 256;
    const int kofs2 = OFF_k + 512;
    const int kofs3 = OFF_k + 768;
    const int kofs4 = OFF_k + 1024;
    const int kofs5 = OFF_k + 256;
    float* kb0 = sm + kofs0;
    float* kb1 = sm + kofs1;
    float* kb2 = sm + kofs2;
    float* kb3 = sm + kofs3;
    float* kb4 = sm + kofs4;
    float* kb5 = sm + kofs5;

    // ============ CDE: 99 intervals x 2 dopri5 substeps ============
    for (int iv = 0; iv < T_ - L_ - 1; iv++) {
        if (tid < 16) {
            int s = L_ + iv;
            float dtv = t[s + 1] - t[s];
            float x0v = (tid < 15) ? cx[(b * T_ + s) * 15 + tid] : t[s];
            float x1v = (tid < 15) ? cx[(b * T_ + s + 1) * 15 + tid] : t[s + 1];
            sdx[tid] = (x1v - x0v) / dtv;
            if (tid == 0) sms[0] = dtv;
        }
        __syncthreads();
        const float hs = sms[0] * 0.5f;

        for (int sub = 0; sub < 2; sub++) {
            // stage 0
            if (tid < 256) szt[tid] = sz[tid];
            __syncthreads();
            vf_eval(sm, kofs0, wid, lane, rank, peer_u32);
            // stage 1
            if (tid < 256) szt[tid] = fmaf(hs * 0.2f, kb0[tid], sz[tid]);
            __syncthreads();
            vf_eval(sm, kofs1, wid, lane, rank, peer_u32);
            // stage 2
            if (tid < 256) {
                float v = 0.075f * kb0[tid] + 0.225f * kb1[tid];
                szt[tid] = fmaf(hs, v, sz[tid]);
            }
            __syncthreads();
            vf_eval(sm, kofs2, wid, lane, rank, peer_u32);
            // stage 3
            if (tid < 256) {
                float v = (44.0f / 45.0f) * kb0[tid] + (-56.0f / 15.0f) * kb1[tid] +
                          (32.0f / 9.0f) * kb2[tid];
                szt[tid] = fmaf(hs, v, sz[tid]);
            }
            __syncthreads();
            vf_eval(sm, kofs3, wid, lane, rank, peer_u32);
            // stage 4
            if (tid < 256) {
                float v = (19372.0f / 6561.0f) * kb0[tid] + (-25360.0f / 2187.0f) * kb1[tid] +
                          (64448.0f / 6561.0f) * kb2[tid] + (-212.0f / 729.0f) * kb3[tid];
                szt[tid] = fmaf(hs, v, sz[tid]);
            }
            __syncthreads();
            vf_eval(sm, kofs4, wid, lane, rank, peer_u32);
            // stage 5 (k1 consumed for the last time; k5 overwrites its slot)
            if (tid < 256) {
                float v = (9017.0f / 3168.0f) * kb0[tid] + (-355.0f / 33.0f) * kb1[tid] +
                          (46732.0f / 5247.0f) * kb2[tid] + (49.0f / 176.0f) * kb3[tid] +
                          (-5103.0f / 18656.0f) * kb4[tid];
                szt[tid] = fmaf(hs, v, sz[tid]);
            }
            __syncthreads();
            vf_eval(sm, kofs5, wid, lane, rank, peer_u32);
            // combine
            if (tid < 256) {
                float v = (35.0f / 384.0f) * kb0[tid] + (500.0f / 1113.0f) * kb2[tid] +
                          (125.0f / 192.0f) * kb3[tid] + (-2187.0f / 6784.0f) * kb4[tid] +
                          (11.0f / 84.0f) * kb5[tid];
                sz[tid] = fmaf(hs, v, sz[tid]);
            }
            __syncthreads();
        }
        readout(iv + 1);
        __syncthreads();
    }
}

extern "C" void kernel_launch(void* const* d_in, const int* in_sizes, int n_in,
                              void* d_out, int out_size) {
    (void)in_sizes;
    (void)n_in;
    (void)out_size;
    const float* w2 = (const float*)d_in[11];
    pack_w2_kernel<<<W2P_ELEMS / 512, 512>>>(w2);
    const size_t smem_bytes = SMEM_FLOATS * sizeof(float);
    cudaFuncSetAttribute(grucde_kernel, cudaFuncAttributeMaxDynamicSharedMemorySize,
                         (int)smem_bytes);
    // 64 clusters x 2 CTAs (cluster dims baked in via __cluster_dims__)
    grucde_kernel<<<2 * B_, NTHREADS, smem_bytes>>>(
        (const float*)d_in[0], (const float*)d_in[1], (const float*)d_in[2],
        (const float*)d_in[3], (const float*)d_in[4], (const float*)d_in[5],
        (const float*)d_in[6], (const float*)d_in[7], (const float*)d_in[8],
        (const float*)d_in[9], (const float*)d_in[10], (const float*)d_in[11],
        (const float*)d_in[12], (const float*)d_in[13], (const float*)d_in[14],
        (float*)d_out);
}

// round 17
// speedup vs baseline: 1.6338x; 1.5011x over previous
#include <cuda_runtime.h>
#include <math.h>

#define B_ 64
#define T_ 200
#define L_ 100
#define S_ 8
#define XC_ 16
#define H_ 256
#define W_ 128
#define O_ 8

#define NCTAS 128
#define NTHREADS 512

typedef unsigned long long u64;

// 2MB packed W2: for h in 0..255, pp in 0..7, k in 0..127:
//   c_lo = (pp&3) + 8*(pp>>2), c_hi = c_lo + 4
#define W2P_ELEMS (2 * 128 * 8 * 256)   // 524288 floats
__device__ float g_W2P[W2P_ELEMS];

// ---------------- global scratch state (no allocs) ----------------
__device__ float g_z[B_ * H_];       // ODE state
__device__ float g_a1[B_ * W_];      // stage-2 activations
__device__ float g_k[6 * B_ * H_];   // k0..k5 [stage][batch][h]
__device__ float g_dx[B_ * XC_];     // dX/dt per interval

// ---------------- software grid barrier (sense-reversing, replay-safe) --------
__device__ unsigned g_count = 0u;
__device__ volatile unsigned g_gen = 0u;

__device__ __forceinline__ void grid_bar() {
    __syncthreads();
    if (threadIdx.x == 0) {
        __threadfence();
        unsigned gen = g_gen;
        if (atomicAdd(&g_count, 1u) == (unsigned)(NCTAS - 1)) {
            g_count = 0u;
            __threadfence();
            g_gen = gen + 1u;
        } else {
            while (g_gen == gen) {}
            __threadfence();
        }
    }
    __syncthreads();
}

// ---------------- round-2 FROZEN math (bit-exact) ----------------
__device__ __forceinline__ float warp_red(float v) {
    v += __shfl_xor_sync(0xffffffffu, v, 16);
    v += __shfl_xor_sync(0xffffffffu, v, 8);
    v += __shfl_xor_sync(0xffffffffu, v, 4);
    v += __shfl_xor_sync(0xffffffffu, v, 2);
    v += __shfl_xor_sync(0xffffffffu, v, 1);
    return v;
}

__device__ __forceinline__ float softplus_(float x) {
    float e = __expf(-fabsf(x));
    return fmaxf(x, 0.0f) + __logf(1.0f + e);
}

__device__ __forceinline__ float sigmoid_(float x) {
    return 1.0f / (1.0f + __expf(-x));
}

// ---------------- packed f32x2 helpers (per-component == scalar fma.rn/add.rn) --
__device__ __forceinline__ u64 ffma2(u64 a, u64 b, u64 c) {
    u64 d;
    asm("fma.rn.f32x2 %0, %1, %2, %3;" : "=l"(d) : "l"(a), "l"(b), "l"(c));
    return d;
}

__device__ __forceinline__ u64 add2(u64 a, u64 b) {
    u64 d;
    asm("add.rn.f32x2 %0, %1, %2;" : "=l"(d) : "l"(a), "l"(b));
    return d;
}

__device__ __forceinline__ u64 dup2(float v) {
    u64 d;
    asm("mov.b64 %0, {%1, %1};" : "=l"(d) : "f"(v));
    return d;
}

__device__ __forceinline__ float2 unpack2(u64 a) {
    float2 r;
    asm("mov.b64 {%0,%1}, %2;" : "=f"(r.x), "=f"(r.y) : "l"(a));
    return r;
}

__device__ __forceinline__ u64 shfl64(u64 v, int m) {
    unsigned lo = (unsigned)v, hi = (unsigned)(v >> 32);
    lo = __shfl_xor_sync(0xffffffffu, lo, m);
    hi = __shfl_xor_sync(0xffffffffu, hi, m);
    return ((u64)hi << 32) | lo;
}

// readout (round-2 arithmetic, verbatim)
__device__ __forceinline__ void readout_(const float* __restrict__ row_,
                                         const float* __restrict__ rob,
                                         float* __restrict__ out,
                                         const float* __restrict__ szs,
                                         int b, int idx, int wid, int lane) {
    if (wid < 8) {
        const float* wr = row_ + wid * 256;
        float v = 0.0f;
#pragma unroll
        for (int k = 0; k < 8; k++) v = fmaf(wr[k * 32 + lane], szs[k * 32 + lane], v);
        v = warp_red(v);
        if (lane == 0) out[(b * L_ + idx) * O_ + wid] = v + rob[wid];
    }
}

extern "C" __global__ void __launch_bounds__(NTHREADS)
grucde_mega(const float* __restrict__ y_past, const float* __restrict__ t,
            const float* __restrict__ cx, const float* __restrict__ wih,
            const float* __restrict__ whh, const float* __restrict__ gb,
            const float* __restrict__ gbn, const float* __restrict__ w0,
            const float* __restrict__ b0, const float* __restrict__ w1,
            const float* __restrict__ b1, const float* __restrict__ w2,
            const float* __restrict__ b2, const float* __restrict__ row_,
            const float* __restrict__ rob, float* __restrict__ out) {
    __shared__ float smem[9600];  // 38.4 KB static (union of phase layouts)
    const int tid = threadIdx.x, wid = tid >> 5, lane = tid & 31;
    const int cta = blockIdx.x;
    const int g = lane >> 3, l8 = lane & 7, odd = l8 & 1;

    // ======== phase 0: pack W2P (128 CTAs x 4096 elems) ========
    for (int i = tid; i < 4096; i += NTHREADS) {
        int idx = cta * 4096 + i;
        int half = idx & 1;
        int k = (idx >> 1) & 127;
        int pp = (idx >> 8) & 7;
        int h = idx >> 11;
        int c = (pp & 3) + 8 * (pp >> 2) + 4 * half;
        g_W2P[idx] = w2[(h * 16 + c) * 128 + k];
    }
    grid_bar();

    // ======== phase 1: GRU encoder (CTAs 0..63; round-9 code verbatim) ========
    if (cta < B_) {
        const int b = cta;
        float* sz = smem;          // 256
        float* sgA = smem + 256;   // 768
        float* sgH = smem + 1024;  // 256
        float* sx = smem + 1280;   // 32
        float* sbn = smem + 1312;  // 256
        if (tid < 256) {
            sbn[tid] = gbn[tid];
            sz[tid] = 0.0f;
        }
        __syncthreads();
        for (int s = 0; s < L_; s++) {
            if (tid < 24) {
                float xv;
                if (tid < 8) xv = y_past[(b * L_ + s) * S_ + tid];
                else if (tid < 23) xv = cx[(b * T_ + s) * (XC_ - 1) + (tid - 8)];
                else xv = t[s];
                sx[tid] = xv;
            }
            __syncthreads();
            for (int row = wid; row < 768; row += 16) {
                float vi = (lane < 24) ? wih[row * 24 + lane] * sx[lane] : 0.0f;
                float vh = 0.0f;
                const float* wr = whh + row * 256;
#pragma unroll
                for (int k = 0; k < 8; k++) vh = fmaf(wr[k * 32 + lane], sz[k * 32 + lane], vh);
                if (row < 512) {
                    float v = warp_red(vi + vh);
                    if (lane == 0) sgA[row] = v + gb[row];
                } else {
                    vi = warp_red(vi);
                    vh = warp_red(vh);
                    if (lane == 0) {
                        sgA[row] = vi + gb[row];
                        sgH[row - 512] = vh;
                    }
                }
            }
            __syncthreads();
            if (tid < 256) {
                int i = tid;
                float r = sigmoid_(sgA[i]);
                float u = sigmoid_(sgA[256 + i]);
                float n = tanhf(fmaf(r, sgH[i] + sbn[i], sgA[512 + i]));
                sz[i] = n + u * (sz[i] - n);
            }
            __syncthreads();
        }
        if (tid < 256) g_z[b * 256 + tid] = sz[tid];
        readout_(row_, rob, out, sz, b, 0, wid, lane);
    }
    grid_bar();

    // ======== CDE: 198 substeps x 6 RK stages, 2 phases each ========
    for (int ss = 0; ss < 198; ss++) {
        const int iv = ss >> 1, sub = ss & 1;
        const int s = L_ + iv;
        for (int st = 0; st < 6; st++) {
            // ---- k12 phase: stage arg + stage1 + stage2 (CTAs 0..63) ----
            if (cta < B_) {
                const int b = cta;
                float* szs = smem;        // 256
                float* szt = smem + 256;  // 256
                float* sa0 = smem + 512;  // 128
                const float* z = g_z + b * 256;
                const float* k0 = g_k + 0 * B_ * H_ + b * 256;
                const float* k1 = g_k + 1 * B_ * H_ + b * 256;
                const float* k2 = g_k + 2 * B_ * H_ + b * 256;
                const float* k3 = g_k + 3 * B_ * H_ + b * 256;
                const float* k4 = g_k + 4 * B_ * H_ + b * 256;
                const float* k5 = g_k + 5 * B_ * H_ + b * 256;
                const float hs = (t[s + 1] - t[s]) * 0.5f;

                if (st == 0) {
                    if (ss > 0) {
                        // update for previous substep (round-2 combine, verbatim)
                        const int pss = ss - 1, piv = pss >> 1, psub = pss & 1;
                        const int sp = L_ + piv;
                        const float hsp = (t[sp + 1] - t[sp]) * 0.5f;
                        if (tid < 256) {
                            const int i = tid;
                            float v = (35.0f / 384.0f) * k0[i] + (500.0f / 1113.0f) * k2[i] +
                                      (125.0f / 192.0f) * k3[i] + (-2187.0f / 6784.0f) * k4[i] +
                                      (11.0f / 84.0f) * k5[i];
                            float zn = fmaf(hsp, v, g_z[b * 256 + i]);
                            g_z[b * 256 + i] = zn;
                            szs[i] = zn;
                        }
                        __syncthreads();
                        if (psub == 1) readout_(row_, rob, out, szs, b, piv + 1, wid, lane);
                    } else {
                        if (tid < 256) szs[tid] = g_z[b * 256 + tid];
                        __syncthreads();
                    }
                    if (sub == 0 && tid < 16) {
                        // dx for this interval (round-2 formula verbatim)
                        float dtv = t[s + 1] - t[s];
                        float x0v = (tid < 15) ? cx[(b * T_ + s) * 15 + tid] : t[s];
                        float x1v = (tid < 15) ? cx[(b * T_ + s + 1) * 15 + tid] : t[s + 1];
                        g_dx[b * 16 + tid] = (x1v - x0v) / dtv;
                    }
                    if (tid < 256) szt[tid] = szs[tid];
                } else if (tid < 256) {
                    const int i = tid;
                    float s_;
                    if (st == 1) {
                        s_ = fmaf(hs * 0.2f, k0[i], z[i]);
                    } else if (st == 2) {
                        float v = 0.075f * k0[i] + 0.225f * k1[i];
                        s_ = fmaf(hs, v, z[i]);
                    } else if (st == 3) {
                        float v = (44.0f / 45.0f) * k0[i] + (-56.0f / 15.0f) * k1[i] +
                                  (32.0f / 9.0f) * k2[i];
                        s_ = fmaf(hs, v, z[i]);
                    } else if (st == 4) {
                        float v = (19372.0f / 6561.0f) * k0[i] + (-25360.0f / 2187.0f) * k1[i] +
                                  (64448.0f / 6561.0f) * k2[i] + (-212.0f / 729.0f) * k3[i];
                        s_ = fmaf(hs, v, z[i]);
                    } else {
                        float v = (9017.0f / 3168.0f) * k0[i] + (-355.0f / 33.0f) * k1[i] +
                                  (46732.0f / 5247.0f) * k2[i] + (49.0f / 176.0f) * k3[i] +
                                  (-5103.0f / 18656.0f) * k4[i];
                        s_ = fmaf(hs, v, z[i]);
                    }
                    szt[i] = s_;
                }
                __syncthreads();

                // stage 1: a0 = softplus(W0 @ szt + b0)  (round-2 chain verbatim)
                for (int row = wid; row < W_; row += 16) {
                    const float* wr = w0 + row * H_;
                    float v = 0.0f;
#pragma unroll
                    for (int k = 0; k < 8; k++)
                        v = fmaf(__ldg(&wr[k * 32 + lane]), szt[k * 32 + lane], v);
                    v = warp_red(v);
                    if (lane == 0) sa0[row] = softplus_(v + __ldg(&b0[row]));
                }
                __syncthreads();

                // stage 2: a1 = softplus(W1 @ a0 + b1)
                for (int row = wid; row < W_; row += 16) {
                    const float* wr = w1 + row * W_;
                    float v = 0.0f;
#pragma unroll
                    for (int k = 0; k < 4; k++)
                        v = fmaf(__ldg(&wr[k * 32 + lane]), sa0[k * 32 + lane], v);
                    v = warp_red(v);
                    if (lane == 0) g_a1[b * 128 + row] = softplus_(v + __ldg(&b1[row]));
                }
            }
            grid_bar();

            // ---- k3 phase: all 128 CTAs, 2 h each, all 64 batches ----
            {
                float* a1_s = smem;         // 8192
                float* dx_s = smem + 8192;  // 1024
                float* b2_s = smem + 9216;  // 32
                {
                    const float4* s4 = (const float4*)g_a1;
                    float4* d = (float4*)a1_s;
                    for (int i = tid; i < 2048; i += NTHREADS) d[i] = s4[i];
                    const float4* sdx4 = (const float4*)g_dx;
                    float4* dd = (float4*)dx_s;
                    if (tid < 256) dd[tid] = sdx4[tid];
                    if (tid < 32) b2_s[tid] = b2[cta * 32 + tid];
                }
                __syncthreads();

                float* kout = g_k + st * B_ * H_;
#pragma unroll
                for (int hh = 0; hh < 2; hh++) {
                    const int h = cta * 2 + hh;
                    float ks[4] = {0.0f, 0.0f, 0.0f, 0.0f};
#pragma unroll
                    for (int q = 0; q < 2; q++) {
                        const float* wp = g_W2P + ((h * 8 + g + 4 * q) << 8) + 8 * l8;
                        float4 wreg[8];
#pragma unroll
                        for (int jj = 0; jj < 4; jj++) {
                            wreg[2 * jj] = __ldg((const float4*)(wp + 64 * jj));
                            wreg[2 * jj + 1] = __ldg((const float4*)(wp + 64 * jj + 4));
                        }
#pragma unroll
                        for (int m = 0; m < 4; m++) {
                            const int mb = wid * 4 + m;
                            const float4* a1v = (const float4*)(a1_s + mb * 128);
                            u64 acc = 0ULL;  // fma(w,a,0) == rn(w*a) == round-2 leading MUL
#pragma unroll
                            for (int jj = 0; jj < 4; jj++) {
                                float4 tt = a1v[jj * 8 + l8];
                                const u64* ua = (const u64*)&wreg[2 * jj];
                                const u64* ub = (const u64*)&wreg[2 * jj + 1];
                                acc = ffma2(ua[0], dup2(tt.x), acc);
                                acc = ffma2(ua[1], dup2(tt.y), acc);
                                acc = ffma2(ub[0], dup2(tt.z), acc);
                                acc = ffma2(ub[1], dup2(tt.w), acc);
                            }
                            // packed xor 1,2,4 reduce (== round-2 scalar tree)
                            acc = add2(acc, shfl64(acc, 1));
                            acc = add2(acc, shfl64(acc, 2));
                            acc = add2(acc, shfl64(acc, 4));
                            float2 sv = unpack2(acc);
                            int c = g + 8 * q + 4 * odd;
                            float bb = b2_s[hh * 16 + c];
                            float x = (odd ? sv.y : sv.x) + bb;
                            float tv = tanhf(x);
                            float tw = __shfl_xor_sync(0xffffffffu, tv, 1);
                            float tvA = odd ? tw : tv;
                            float tvB = odd ? tv : tw;
                            ks[m] = fmaf(tvA, dx_s[mb * 16 + 8 * q + g], ks[m]);
                            ks[m] = fmaf(tvB, dx_s[mb * 16 + 8 * q + 4 + g], ks[m]);
                        }
                    }
#pragma unroll
                    for (int m = 0; m < 4; m++) {
                        float kv = ks[m];
                        kv += __shfl_xor_sync(0xffffffffu, kv, 8);
                        kv += __shfl_xor_sync(0xffffffffu, kv, 16);
                        if (lane == 0) kout[(wid * 4 + m) * 256 + h] = kv;
                    }
                }
            }
            grid_bar();
        }
    }

    // ======== epilogue: update for substep 197 + readout(99) ========
    if (cta < B_) {
        const int b = cta;
        float* szs = smem;
        const int sp = L_ + 98;
        const float hsp = (t[sp + 1] - t[sp]) * 0.5f;
        const float* k0 = g_k + 0 * B_ * H_ + b * 256;
        const float* k2 = g_k + 2 * B_ * H_ + b * 256;
        const float* k3 = g_k + 3 * B_ * H_ + b * 256;
        const float* k4 = g_k + 4 * B_ * H_ + b * 256;
        const float* k5 = g_k + 5 * B_ * H_ + b * 256;
        if (tid < 256) {
            const int i = tid;
            float v = (35.0f / 384.0f) * k0[i] + (500.0f / 1113.0f) * k2[i] +
                      (125.0f / 192.0f) * k3[i] + (-2187.0f / 6784.0f) * k4[i] +
                      (11.0f / 84.0f) * k5[i];
            float zn = fmaf(hsp, v, g_z[b * 256 + i]);
            g_z[b * 256 + i] = zn;
            szs[i] = zn;
        }
        __syncthreads();
        readout_(row_, rob, out, szs, b, 99, wid, lane);
    }
}

extern "C" void kernel_launch(void* const* d_in, const int* in_sizes, int n_in,
                              void* d_out, int out_size) {
    (void)in_sizes;
    (void)n_in;
    (void)out_size;
    grucde_mega<<<NCTAS, NTHREADS>>>(
        (const float*)d_in[0], (const float*)d_in[1], (const float*)d_in[2],
        (const float*)d_in[3], (const float*)d_in[4], (const float*)d_in[5],
        (const float*)d_in[6], (const float*)d_in[7], (const float*)d_in[8],
        (const float*)d_in[9], (const float*)d_in[10], (const float*)d_in[11],
        (const float*)d_in[12], (const float*)d_in[13], (const float*)d_in[14],
        (float*)d_out);
}